// round 4
// baseline (speedup 1.0000x reference)
#include <cuda_runtime.h>

#define NN   50000
#define EE   800000
#define HH   64
#define EAD  16
#define LLAY 5
#define GG   512
#define IN2  80
#define FD   320   // L*H
#define NBLK 49    // ceil(NN/1024)
#define CHK  256   // edges staged per kAgg chunk

typedef unsigned long long ull;

// ---------------- device scratch ----------------
__device__ int   g_flag64;
__device__ int   g_cnt[NN];
__device__ int   g_off[NN + 1];
__device__ int   g_cur[NN];
__device__ int   g_bsum[NBLK];
__device__ int   g_srcS[EE];
__device__ __align__(16) float g_eaS[(size_t)EE * EAD];   // edge_attr sorted by dst
__device__ __align__(16) float g_t1[(size_t)NN * HH];     // x@W1a + b1
__device__ __align__(16) float g_agg[(size_t)NN * HH];
__device__ __align__(16) float g_xA[(size_t)NN * HH];
__device__ __align__(16) float g_xB[(size_t)NN * HH];
__device__ float g_pool[(size_t)GG * FD];

// ---------------- f32x2 packed helpers ----------------
__device__ __forceinline__ ull pk2(float a, float b) {
    ull r; asm("mov.b64 %0,{%1,%2};" : "=l"(r) : "f"(a), "f"(b)); return r;
}
__device__ __forceinline__ void upk2(ull v, float& a, float& b) {
    asm("mov.b64 {%0,%1},%2;" : "=f"(a), "=f"(b) : "l"(v));
}
__device__ __forceinline__ ull fma2(ull a, ull b, ull c) {
    ull d; asm("fma.rn.f32x2 %0,%1,%2,%3;" : "=l"(d) : "l"(a), "l"(b), "l"(c)); return d;
}

__device__ __forceinline__ int loadIdx(const void* p, long long i, int is64) {
    if (is64) return (int)((const long long*)p)[i];
    return ((const int*)p)[i];
}
__device__ __forceinline__ const float* pickIn(int sel, const float* xin) {
    switch (sel) { case 2: return g_xA; case 3: return g_xB; default: return xin; }
}
__device__ __forceinline__ float* pickOut(int sel) { return (sel == 2) ? g_xA : g_xB; }

// ---------------- setup ----------------
__global__ void kDetect(const void* ei) {
    const int* p = (const int*)ei;
    g_flag64 = (p[1] == 0 && p[3] == 0 && p[5] == 0 && p[7] == 0) ? 1 : 0;
}
__global__ void kZero() {
    int i = blockIdx.x * blockDim.x + threadIdx.x;
    if (i < NN) g_cnt[i] = 0;
    if (i < GG * FD) g_pool[i] = 0.f;
}
__global__ void kCount(const void* __restrict__ ei) {
    int e = blockIdx.x * blockDim.x + threadIdx.x;
    if (e >= EE) return;
    int f = g_flag64;
    int s = loadIdx(ei, e, f);
    int d = loadIdx(ei, (long long)EE + e, f);
    if (s != d) atomicAdd(&g_cnt[d], 1);
}
__global__ void kScanA() {
    __shared__ int wsum[32];
    int tid = threadIdx.x, lane = tid & 31, wid = tid >> 5;
    int i = blockIdx.x * 1024 + tid;
    int v = (i < NN) ? g_cnt[i] : 0;
    int x = v;
#pragma unroll
    for (int o = 1; o < 32; o <<= 1) {
        int t = __shfl_up_sync(0xffffffffu, x, o);
        if (lane >= o) x += t;
    }
    if (lane == 31) wsum[wid] = x;
    __syncthreads();
    if (tid < 32) {
        int y = wsum[tid];
#pragma unroll
        for (int o = 1; o < 32; o <<= 1) {
            int t = __shfl_up_sync(0xffffffffu, y, o);
            if (tid >= o) y += t;
        }
        wsum[tid] = y;
    }
    __syncthreads();
    int incl = x + (wid ? wsum[wid - 1] : 0);
    if (i < NN) g_off[i] = incl - v;
    if (tid == 1023) g_bsum[blockIdx.x] = incl;
}
__global__ void kScanB() {
    if (threadIdx.x == 0) {
        int s = 0;
        for (int b = 0; b < NBLK; b++) { int t = g_bsum[b]; g_bsum[b] = s; s += t; }
        g_off[NN] = s;
    }
}
__global__ void kScanC() {
    int i = blockIdx.x * 1024 + threadIdx.x;
    if (i < NN) {
        int v = g_off[i] + g_bsum[blockIdx.x];
        g_off[i] = v;
        g_cur[i] = v;
    }
}
__global__ void kScatter(const void* __restrict__ ei, const float* __restrict__ ea) {
    int e = blockIdx.x * blockDim.x + threadIdx.x;
    if (e >= EE) return;
    int f = g_flag64;
    int s = loadIdx(ei, e, f);
    int d = loadIdx(ei, (long long)EE + e, f);
    if (s == d) return;
    int pos = atomicAdd(&g_cur[d], 1);
    g_srcS[pos] = s;
    const float4* s4 = (const float4*)(ea + (size_t)e * EAD);
    float4* d4 = (float4*)(g_eaS + (size_t)pos * EAD);
    d4[0] = s4[0]; d4[1] = s4[1]; d4[2] = s4[2]; d4[3] = s4[3];
}

// ---------------- shared-weight packed GEMM core (32-row tile) ----------------
// sIn[rp][k] (ull) = (row 2rp [k], row 2rp+1 [k]), rp in 0..15, k in 0..63.
// wD[kp*64 + cc] (ulonglong2) = ( dup(W[2kp][cc]), dup(W[2kp+1][cc]) ).
// thread: c = tid&31 -> cols {c, c+32};  rw = tid>>5 -> rowpairs {rw, rw+8}.
// acc[0]=(rw,c) acc[1]=(rw,c+32) acc[2]=(rw+8,c) acc[3]=(rw+8,c+32)
__device__ __forceinline__ void gemm32(const ull (*sIn)[64], const ulonglong2* wD,
                                       int c, int rw, ull* acc) {
    acc[0] = acc[1] = acc[2] = acc[3] = 0ull;
#pragma unroll
    for (int kp = 0; kp < 32; kp++) {
        ulonglong2 wa = wD[kp * 64 + c];
        ulonglong2 wb = wD[kp * 64 + c + 32];
        ulonglong2 v0 = *(const ulonglong2*)&sIn[rw][2 * kp];
        ulonglong2 v1 = *(const ulonglong2*)&sIn[rw + 8][2 * kp];
        acc[0] = fma2(v0.x, wa.x, acc[0]);
        acc[0] = fma2(v0.y, wa.y, acc[0]);
        acc[1] = fma2(v0.x, wb.x, acc[1]);
        acc[1] = fma2(v0.y, wb.y, acc[1]);
        acc[2] = fma2(v1.x, wa.x, acc[2]);
        acc[2] = fma2(v1.y, wa.y, acc[2]);
        acc[3] = fma2(v1.x, wb.x, acc[3]);
        acc[3] = fma2(v1.y, wb.y, acc[3]);
    }
}

// stage 64x64 row-major weights into pre-duplicated packed form
__device__ __forceinline__ void stageW(const float* __restrict__ W, ulonglong2* wD, int tid) {
    for (int i = tid; i < 2048; i += 256) {
        int kp = i >> 6, cc = i & 63;
        float w0 = W[(2 * kp) * HH + cc];
        float w1 = W[(2 * kp + 1) * HH + cc];
        ulonglong2 t; t.x = pk2(w0, w0); t.y = pk2(w1, w1);
        wD[i] = t;
    }
}

// stage 32 rows of a row-major [*,64] matrix into rowpair-packed smem
__device__ __forceinline__ void stageX(const float* __restrict__ src, float* sf,
                                       int base, int tid) {
    for (int i = tid; i < 2048; i += 256) {
        int r = i >> 6, cc = i & 63;
        int gr = base + r;
        sf[((r >> 1) * 64 + cc) * 2 + (r & 1)] = (gr < NN) ? src[(size_t)gr * HH + cc] : 0.f;
    }
}

// ---------------- t1 = x @ W1a + b1 ----------------
__global__ __launch_bounds__(256) void kT1(const float* __restrict__ X,
                                           const float* __restrict__ W,
                                           const float* __restrict__ B) {
    __shared__ __align__(16) ull sIn[16][64];
    __shared__ __align__(16) ulonglong2 wD[2048];
    int tid = threadIdx.x, c = tid & 31, rw = tid >> 5;
    int base = blockIdx.x * 32;
    stageX(X, (float*)sIn, base, tid);
    stageW(W, wD, tid);
    __syncthreads();
    ull acc[4];
    gemm32(sIn, wD, c, rw, acc);
    float bc = B[c], bc2 = B[c + 32];
#pragma unroll
    for (int j = 0; j < 4; j++) {
        int rp = (j < 2) ? rw : rw + 8;
        int col = (j & 1) ? c + 32 : c;
        float bb = (j & 1) ? bc2 : bc;
        int r0 = base + 2 * rp, r1 = r0 + 1;
        float a0, a1; upk2(acc[j], a0, a1);
        if (r0 < NN) g_t1[(size_t)r0 * HH + col] = a0 + bb;
        if (r1 < NN) g_t1[(size_t)r1 * HH + col] = a1 + bb;
    }
}

// ---------------- edge aggregation: smem-staged ea, 4-deep gather ring ----------------
__global__ __launch_bounds__(256) void kAgg(const float* __restrict__ w1full) {
    __shared__ __align__(16) float sea[CHK * EAD];   // 16 KB
    __shared__ int ssrc[CHK];
    int tid = threadIdx.x;
    int lane = tid & 31, warp = tid >> 5;
    const float* w1b = w1full + 64 * HH;             // rows 64..79 of 80x64
    ull wA2[8], wB2[8];
#pragma unroll
    for (int p = 0; p < 8; p++) {
        wA2[p] = pk2(w1b[(2 * p) * HH + lane],      w1b[(2 * p + 1) * HH + lane]);
        wB2[p] = pk2(w1b[(2 * p) * HH + lane + 32], w1b[(2 * p + 1) * HH + lane + 32]);
    }
    int nb = blockIdx.x * 8;
    int n = nb + warp;
    int beg = g_off[n], end = g_off[n + 1];
    int bBeg = g_off[nb], bEnd = g_off[nb + 8];
    float accA = 0.f, accB = 0.f;

    for (int cb = bBeg; cb < bEnd; cb += CHK) {
        int cnt = min(CHK, bEnd - cb);
        __syncthreads();
        for (int i = tid; i < cnt * 4; i += 256)
            ((float4*)sea)[i] = ((const float4*)g_eaS)[(size_t)cb * 4 + i];
        for (int i = tid; i < cnt; i += 256) ssrc[i] = g_srcS[cb + i];
        __syncthreads();

        int myB = max(beg, cb), myE = min(end, cb + cnt);
        int m = myE - myB;
        if (m > 0) {
            int q0 = myB - cb;
            float pa[4], pb[4];
#pragma unroll
            for (int d = 0; d < 4; d++) {
                if (d < m) {
                    int s = ssrc[q0 + d];
                    pa[d] = g_t1[(size_t)s * HH + lane];
                    pb[d] = g_t1[(size_t)s * HH + lane + 32];
                } else { pa[d] = 0.f; pb[d] = 0.f; }
            }
#pragma unroll 4
            for (int e = 0; e < m; e++) {
                int d = e & 3;
                float ga = pa[d], gb = pb[d];
                if (e + 4 < m) {
                    int s = ssrc[q0 + e + 4];
                    pa[d] = g_t1[(size_t)s * HH + lane];
                    pb[d] = g_t1[(size_t)s * HH + lane + 32];
                }
                const ulonglong2* ep = (const ulonglong2*)(sea + (size_t)(q0 + e) * EAD);
                ull tA = pk2(ga, 0.f), tB = pk2(gb, 0.f);
#pragma unroll
                for (int p = 0; p < 4; p++) {
                    ulonglong2 v = ep[p];
                    tA = fma2(v.x, wA2[2 * p], tA);
                    tB = fma2(v.x, wB2[2 * p], tB);
                    tA = fma2(v.y, wA2[2 * p + 1], tA);
                    tB = fma2(v.y, wB2[2 * p + 1], tB);
                }
                float a0, a1, b0v, b1v;
                upk2(tA, a0, a1); upk2(tB, b0v, b1v);
                accA += fmaxf(a0 + a1, 0.f);
                accB += fmaxf(b0v + b1v, 0.f);
            }
        }
    }
    g_agg[(size_t)n * HH + lane] = accA;
    g_agg[(size_t)n * HH + lane + 32] = accB;
}

// ---------------- fused node update (smem weights, 4 stages) ----------------
__global__ __launch_bounds__(256) void kNode(int xSel, const float* __restrict__ xExt,
                                             int xOutSel,
                                             const float* __restrict__ W2,
                                             const float* __restrict__ b2,
                                             const float* __restrict__ V1,
                                             const float* __restrict__ c1,
                                             const float* __restrict__ V2,
                                             const float* __restrict__ c2,
                                             const float* __restrict__ W1n,
                                             const float* __restrict__ b1n,
                                             const float* __restrict__ epsPtr,
                                             const void* __restrict__ batch, int layer) {
    __shared__ __align__(16) ull sA[16][64];           // 8 KB
    __shared__ __align__(16) ull sB[16][64];           // 8 KB
    __shared__ __align__(16) ulonglong2 wD[2048];      // 32 KB
    int tid = threadIdx.x, c = tid & 31, rw = tid >> 5;
    int base = blockIdx.x * 32;
    const float* X = pickIn(xSel, xExt);
    float* Xo = pickOut(xOutSel);
    ull acc[4];

    stageX(g_agg, (float*)sA, base, tid);
    stageW(W2, wD, tid);
    __syncthreads();

    // ---- stage 1: u = agg@W2 + (1+eps)*x + cnt*b2 -> sB ----
    gemm32(sA, wD, c, rw, acc);
    {
        float ope = 1.f + epsPtr[0];
        float b0 = b2[c], b1v = b2[c + 32];
#pragma unroll
        for (int j = 0; j < 4; j++) {
            int rp = (j < 2) ? rw : rw + 8;
            int col = (j & 1) ? c + 32 : c;
            float bb = (j & 1) ? b1v : b0;
            int r0 = base + 2 * rp, r1 = r0 + 1;
            float a0, a1; upk2(acc[j], a0, a1);
            float x0 = (r0 < NN) ? X[(size_t)r0 * HH + col] : 0.f;
            float x1 = (r1 < NN) ? X[(size_t)r1 * HH + col] : 0.f;
            float n0 = (r0 < NN) ? (float)g_cnt[r0] : 0.f;
            float n1 = (r1 < NN) ? (float)g_cnt[r1] : 0.f;
            sB[rp][col] = pk2(a0 + ope * x0 + n0 * bb, a1 + ope * x1 + n1 * bb);
        }
    }
    __syncthreads();
    stageW(V1, wD, tid);
    __syncthreads();

    // ---- stage 2: h = relu(u@V1 + c1) -> sA ----
    gemm32(sB, wD, c, rw, acc);
    {
        float b0 = c1[c], b1v = c1[c + 32];
#pragma unroll
        for (int j = 0; j < 4; j++) {
            int rp = (j < 2) ? rw : rw + 8;
            int col = (j & 1) ? c + 32 : c;
            float bb = (j & 1) ? b1v : b0;
            float a0, a1; upk2(acc[j], a0, a1);
            sA[rp][col] = pk2(fmaxf(a0 + bb, 0.f), fmaxf(a1 + bb, 0.f));
        }
    }
    __syncthreads();
    stageW(V2, wD, tid);
    __syncthreads();

    // ---- stage 3: xn = h@V2 + c2 -> sB + global + pool ----
    gemm32(sA, wD, c, rw, acc);
    {
        float b0 = c2[c], b1v = c2[c + 32];
        int f64 = g_flag64;
#pragma unroll
        for (int j = 0; j < 4; j++) {
            int rp = (j < 2) ? rw : rw + 8;
            int col = (j & 1) ? c + 32 : c;
            float bb = (j & 1) ? b1v : b0;
            int r0 = base + 2 * rp, r1 = r0 + 1;
            float a0, a1; upk2(acc[j], a0, a1);
            float v0 = a0 + bb, v1 = a1 + bb;
            sB[rp][col] = pk2(v0, v1);
            if (r0 < NN) {
                Xo[(size_t)r0 * HH + col] = v0;
                int g = f64 ? (int)((const long long*)batch)[r0] : ((const int*)batch)[r0];
                atomicAdd(&g_pool[(size_t)g * FD + layer * HH + col], v0);
            }
            if (r1 < NN) {
                Xo[(size_t)r1 * HH + col] = v1;
                int g = f64 ? (int)((const long long*)batch)[r1] : ((const int*)batch)[r1];
                atomicAdd(&g_pool[(size_t)g * FD + layer * HH + col], v1);
            }
        }
    }

    // ---- stage 4: t1_next = xn@W1a_next + b1_next ----
    if (W1n) {
        __syncthreads();
        stageW(W1n, wD, tid);
        __syncthreads();
        gemm32(sB, wD, c, rw, acc);
        float b0 = b1n[c], b1v = b1n[c + 32];
#pragma unroll
        for (int j = 0; j < 4; j++) {
            int rp = (j < 2) ? rw : rw + 8;
            int col = (j & 1) ? c + 32 : c;
            float bb = (j & 1) ? b1v : b0;
            int r0 = base + 2 * rp, r1 = r0 + 1;
            float a0, a1; upk2(acc[j], a0, a1);
            if (r0 < NN) g_t1[(size_t)r0 * HH + col] = a0 + bb;
            if (r1 < NN) g_t1[(size_t)r1 * HH + col] = a1 + bb;
        }
    }
}

// ---------------- final MLP ----------------
__global__ __launch_bounds__(320) void kFinal(const float* __restrict__ fw1,
                                              const float* __restrict__ fb1,
                                              const float* __restrict__ fw2,
                                              const float* __restrict__ fb2,
                                              float* __restrict__ out) {
    __shared__ float fsh[8][FD];
    __shared__ float hsh[8][FD];
    int tid = threadIdx.x;
    int gbase = blockIdx.x * 8;
    for (int i = tid; i < 8 * FD; i += 320) {
        int gg = i / FD, k = i % FD;
        fsh[gg][k] = g_pool[(size_t)(gbase + gg) * FD + k];
    }
    __syncthreads();
    float acc[8] = {0, 0, 0, 0, 0, 0, 0, 0};
    for (int k = 0; k < FD; k++) {
        float w = fw1[(size_t)k * FD + tid];
#pragma unroll
        for (int gg = 0; gg < 8; gg++) acc[gg] = fmaf(fsh[gg][k], w, acc[gg]);
    }
    float b = fb1[tid];
#pragma unroll
    for (int gg = 0; gg < 8; gg++) hsh[gg][tid] = fmaxf(acc[gg] + b, 0.f);
    __syncthreads();
    int warp = tid >> 5, lane = tid & 31;
    if (warp < 8) {
        float s = 0.f;
        for (int k = lane; k < FD; k += 32) s += hsh[warp][k] * fw2[k];
#pragma unroll
        for (int o = 16; o; o >>= 1) s += __shfl_down_sync(0xffffffffu, s, o);
        if (lane == 0) out[gbase + warp] = s + fb2[0];
    }
}

// ---------------- launch ----------------
extern "C" void kernel_launch(void* const* d_in, const int* in_sizes, int n_in,
                              void* d_out, int out_size) {
    const float* x    = (const float*)d_in[0];
    const void*  ei   = d_in[1];
    const float* ea   = (const float*)d_in[2];
    const void*  bat  = d_in[3];
    const float* n2w1 = (const float*)d_in[4];
    const float* n2b1 = (const float*)d_in[5];
    const float* n2w2 = (const float*)d_in[6];
    const float* n2b2 = (const float*)d_in[7];
    const float* n1w1 = (const float*)d_in[8];
    const float* n1b1 = (const float*)d_in[9];
    const float* n1w2 = (const float*)d_in[10];
    const float* n1b2 = (const float*)d_in[11];
    const float* fw1  = (const float*)d_in[12];
    const float* fb1  = (const float*)d_in[13];
    const float* fw2  = (const float*)d_in[14];
    const float* fb2  = (const float*)d_in[15];
    const float* eps  = (const float*)d_in[16];

    kDetect<<<1, 1>>>(ei);
    kZero<<<(GG * FD + 255) / 256, 256>>>();
    kCount<<<EE / 256, 256>>>(ei);
    // launch #4 = kT1 so ncu captures the new GEMM core
    kT1<<<(NN + 31) / 32, 256>>>(x, n2w1, n2b1);
    kScanA<<<NBLK, 1024>>>();
    kScanB<<<1, 32>>>();
    kScanC<<<NBLK, 1024>>>();
    kScatter<<<EE / 256, 256>>>(ei, ea);

    int xSel = 4;
    const float* xPtr = x;
    for (int l = 0; l < LLAY; l++) {
        const float* W2 = n2w2 + (size_t)l * HH * HH;
        const float* b2 = n2b2 + (size_t)l * HH;
        const float* V1 = n1w1 + (size_t)l * HH * HH;
        const float* c1 = n1b1 + (size_t)l * HH;
        const float* V2 = n1w2 + (size_t)l * HH * HH;
        const float* c2 = n1b2 + (size_t)l * HH;
        const float* W1n = (l + 1 < LLAY) ? n2w1 + (size_t)(l + 1) * IN2 * HH : nullptr;
        const float* b1n = (l + 1 < LLAY) ? n2b1 + (size_t)(l + 1) * HH : nullptr;
        int xNextSel = (l & 1) ? 3 : 2;

        kAgg<<<NN / 8, 256>>>(n2w1 + (size_t)l * IN2 * HH);
        kNode<<<(NN + 31) / 32, 256>>>(xSel, xPtr, xNextSel, W2, b2, V1, c1, V2, c2,
                                       W1n, b1n, eps, bat, l);

        xSel = xNextSel;
        xPtr = nullptr;
    }

    kFinal<<<GG / 8, 320>>>(fw1, fb1, fw2, fb2, (float*)d_out);
}

// round 5
// speedup vs baseline: 1.3439x; 1.3439x over previous
#include <cuda_runtime.h>

#define NN   50000
#define EE   800000
#define HH   64
#define EAD  16
#define LLAY 5
#define GG   512
#define IN2  80
#define FD   320   // L*H
#define NBLK 49    // ceil(NN/1024)
#define CHK  256   // edges staged per kAgg chunk

typedef unsigned long long ull;

// ---------------- device scratch ----------------
__device__ int   g_flag64;
__device__ int   g_cnt[NN];
__device__ int   g_off[NN + 1];
__device__ int   g_cur[NN];
__device__ int   g_bsum[NBLK];
__device__ int   g_srcS[EE];
__device__ __align__(16) float g_eaS[(size_t)EE * EAD];   // edge_attr sorted by dst
__device__ __align__(16) float g_t1[(size_t)NN * HH];     // x@W1a + b1
__device__ __align__(16) float g_agg[(size_t)NN * HH];
__device__ __align__(16) float g_xA[(size_t)NN * HH];
__device__ __align__(16) float g_xB[(size_t)NN * HH];
__device__ float g_pool[(size_t)GG * FD];

// ---------------- f32x2 packed helpers ----------------
__device__ __forceinline__ ull pk2(float a, float b) {
    ull r; asm("mov.b64 %0,{%1,%2};" : "=l"(r) : "f"(a), "f"(b)); return r;
}
__device__ __forceinline__ void upk2(ull v, float& a, float& b) {
    asm("mov.b64 {%0,%1},%2;" : "=f"(a), "=f"(b) : "l"(v));
}
__device__ __forceinline__ ull fma2(ull a, ull b, ull c) {
    ull d; asm("fma.rn.f32x2 %0,%1,%2,%3;" : "=l"(d) : "l"(a), "l"(b), "l"(c)); return d;
}

__device__ __forceinline__ int loadIdx(const void* p, long long i, int is64) {
    if (is64) return (int)((const long long*)p)[i];
    return ((const int*)p)[i];
}
__device__ __forceinline__ const float* pickIn(int sel, const float* xin) {
    switch (sel) { case 2: return g_xA; case 3: return g_xB; default: return xin; }
}
__device__ __forceinline__ float* pickOut(int sel) { return (sel == 2) ? g_xA : g_xB; }

// ---------------- setup ----------------
__global__ void kDetect(const void* ei) {
    const int* p = (const int*)ei;
    g_flag64 = (p[1] == 0 && p[3] == 0 && p[5] == 0 && p[7] == 0) ? 1 : 0;
}
__global__ void kZero() {
    int i = blockIdx.x * blockDim.x + threadIdx.x;
    if (i < NN) g_cnt[i] = 0;
    if (i < GG * FD) g_pool[i] = 0.f;
}
__global__ void kCount(const void* __restrict__ ei) {
    int e = blockIdx.x * blockDim.x + threadIdx.x;
    if (e >= EE) return;
    int f = g_flag64;
    int s = loadIdx(ei, e, f);
    int d = loadIdx(ei, (long long)EE + e, f);
    if (s != d) atomicAdd(&g_cnt[d], 1);
}
__global__ void kScanA() {
    __shared__ int wsum[32];
    int tid = threadIdx.x, lane = tid & 31, wid = tid >> 5;
    int i = blockIdx.x * 1024 + tid;
    int v = (i < NN) ? g_cnt[i] : 0;
    int x = v;
#pragma unroll
    for (int o = 1; o < 32; o <<= 1) {
        int t = __shfl_up_sync(0xffffffffu, x, o);
        if (lane >= o) x += t;
    }
    if (lane == 31) wsum[wid] = x;
    __syncthreads();
    if (tid < 32) {
        int y = wsum[tid];
#pragma unroll
        for (int o = 1; o < 32; o <<= 1) {
            int t = __shfl_up_sync(0xffffffffu, y, o);
            if (tid >= o) y += t;
        }
        wsum[tid] = y;
    }
    __syncthreads();
    int incl = x + (wid ? wsum[wid - 1] : 0);
    if (i < NN) g_off[i] = incl - v;
    if (tid == 1023) g_bsum[blockIdx.x] = incl;
}
__global__ void kScanB() {
    if (threadIdx.x == 0) {
        int s = 0;
        for (int b = 0; b < NBLK; b++) { int t = g_bsum[b]; g_bsum[b] = s; s += t; }
        g_off[NN] = s;
    }
}
__global__ void kScanC() {
    int i = blockIdx.x * 1024 + threadIdx.x;
    if (i < NN) {
        int v = g_off[i] + g_bsum[blockIdx.x];
        g_off[i] = v;
        g_cur[i] = v;
    }
}
__global__ void kScatter(const void* __restrict__ ei, const float* __restrict__ ea) {
    int e = blockIdx.x * blockDim.x + threadIdx.x;
    if (e >= EE) return;
    int f = g_flag64;
    int s = loadIdx(ei, e, f);
    int d = loadIdx(ei, (long long)EE + e, f);
    if (s == d) return;
    int pos = atomicAdd(&g_cur[d], 1);
    g_srcS[pos] = s;
    const float4* s4 = (const float4*)(ea + (size_t)e * EAD);
    float4* d4 = (float4*)(g_eaS + (size_t)pos * EAD);
    d4[0] = s4[0]; d4[1] = s4[1]; d4[2] = s4[2]; d4[3] = s4[3];
}

// ---------------- packed 32-row GEMM core, two-phase weight regs ----------------
// sIn[rp][k] = f32x2(row 2rp [k], row 2rp+1 [k]).  thread (c=tid&63, rs=tid>>6)
// computes col c of rowpairs {rs, rs+4, rs+8, rs+12}.  Weights are loaded
// 32-at-a-time (half of K) so they stay register-resident (no spill).
__device__ __forceinline__ void gemmP(const ull (*sIn)[64], const float* __restrict__ W,
                                      int c, int rs, ull* acc) {
#pragma unroll
    for (int i = 0; i < 4; i++) acc[i] = 0ull;
#pragma unroll 1
    for (int h = 0; h < 2; h++) {
        float w[32];
#pragma unroll
        for (int k = 0; k < 32; k++) w[k] = W[(32 * h + k) * HH + c];
#pragma unroll
        for (int kp = 0; kp < 16; kp++) {
            ull wd0 = pk2(w[2 * kp], w[2 * kp]);
            ull wd1 = pk2(w[2 * kp + 1], w[2 * kp + 1]);
#pragma unroll
            for (int i = 0; i < 4; i++) {
                ulonglong2 v = *(const ulonglong2*)&sIn[rs + 4 * i][32 * h + 2 * kp];
                acc[i] = fma2(v.x, wd0, acc[i]);
                acc[i] = fma2(v.y, wd1, acc[i]);
            }
        }
    }
}

// stage 32 rows of a row-major [*,64] matrix into rowpair-packed smem
__device__ __forceinline__ void stageX(const float* __restrict__ src, float* sf,
                                       int base, int tid) {
    for (int i = tid; i < 2048; i += 256) {
        int r = i >> 6, cc = i & 63;
        int gr = base + r;
        sf[((r >> 1) * 64 + cc) * 2 + (r & 1)] = (gr < NN) ? src[(size_t)gr * HH + cc] : 0.f;
    }
}

// ---------------- t1 = x @ W1a + b1 ----------------
__global__ __launch_bounds__(256) void kT1(const float* __restrict__ X,
                                           const float* __restrict__ W,
                                           const float* __restrict__ B) {
    __shared__ __align__(16) ull sIn[16][64];
    int tid = threadIdx.x;
    int c = tid & 63, rs = tid >> 6;
    int base = blockIdx.x * 32;
    stageX(X, (float*)sIn, base, tid);
    __syncthreads();
    ull acc[4];
    gemmP(sIn, W, c, rs, acc);
    float b = B[c];
#pragma unroll
    for (int i = 0; i < 4; i++) {
        int r0 = base + 2 * (rs + 4 * i), r1 = r0 + 1;
        float a0, a1; upk2(acc[i], a0, a1);
        if (r0 < NN) g_t1[(size_t)r0 * HH + c] = a0 + b;
        if (r1 < NN) g_t1[(size_t)r1 * HH + c] = a1 + b;
    }
}

// ---------------- edge aggregation: smem-staged, 3-deep gather prefetch ----------------
// agg[n][c] = sum over incoming non-self edges of relu(t1[src][c] + (ea@W1b)[c])
__global__ __launch_bounds__(256) void kAgg(const float* __restrict__ w1full) {
    __shared__ __align__(16) float sea[CHK * EAD];   // 16 KB
    __shared__ int ssrc[CHK];
    int tid = threadIdx.x;
    int lane = tid & 31, warp = tid >> 5;
    const float* w1b = w1full + 64 * HH;             // rows 64..79 of 80x64
    ull wA2[8], wB2[8];
#pragma unroll
    for (int p = 0; p < 8; p++) {
        wA2[p] = pk2(w1b[(2 * p) * HH + lane],      w1b[(2 * p + 1) * HH + lane]);
        wB2[p] = pk2(w1b[(2 * p) * HH + lane + 32], w1b[(2 * p + 1) * HH + lane + 32]);
    }
    int nb = blockIdx.x * 8;
    int n = nb + warp;
    int beg = g_off[n], end = g_off[n + 1];
    int bBeg = g_off[nb], bEnd = g_off[nb + 8];
    float accA = 0.f, accB = 0.f;

    for (int cb = bBeg; cb < bEnd; cb += CHK) {
        int cnt = min(CHK, bEnd - cb);
        __syncthreads();
        for (int i = tid; i < cnt * 4; i += 256)
            ((float4*)sea)[i] = ((const float4*)g_eaS)[(size_t)cb * 4 + i];
        for (int i = tid; i < cnt; i += 256) ssrc[i] = g_srcS[cb + i];
        __syncthreads();

        int myB = max(beg, cb), myE = min(end, cb + cnt);
        int m = myE - myB;
        if (m > 0) {
            int q0 = myB - cb;
            float ga0, gb0, ga1 = 0.f, gb1 = 0.f, ga2 = 0.f, gb2 = 0.f;
            { int s = ssrc[q0];
              ga0 = g_t1[(size_t)s * HH + lane]; gb0 = g_t1[(size_t)s * HH + lane + 32]; }
            if (m > 1) { int s = ssrc[q0 + 1];
              ga1 = g_t1[(size_t)s * HH + lane]; gb1 = g_t1[(size_t)s * HH + lane + 32]; }
            if (m > 2) { int s = ssrc[q0 + 2];
              ga2 = g_t1[(size_t)s * HH + lane]; gb2 = g_t1[(size_t)s * HH + lane + 32]; }
            for (int q = 0; q < m; q++) {
                float nga = 0.f, ngb = 0.f;
                if (q + 3 < m) {
                    int s = ssrc[q0 + q + 3];
                    nga = g_t1[(size_t)s * HH + lane];
                    ngb = g_t1[(size_t)s * HH + lane + 32];
                }
                const ulonglong2* ep = (const ulonglong2*)(sea + (size_t)(q0 + q) * EAD);
                ull tA = pk2(ga0, 0.f), tB = pk2(gb0, 0.f);
#pragma unroll
                for (int p = 0; p < 4; p++) {
                    ulonglong2 v = ep[p];
                    tA = fma2(v.x, wA2[2 * p], tA);
                    tB = fma2(v.x, wB2[2 * p], tB);
                    tA = fma2(v.y, wA2[2 * p + 1], tA);
                    tB = fma2(v.y, wB2[2 * p + 1], tB);
                }
                float a0, a1, b0, b1;
                upk2(tA, a0, a1); upk2(tB, b0, b1);
                accA += fmaxf(a0 + a1, 0.f);
                accB += fmaxf(b0 + b1, 0.f);
                ga0 = ga1; gb0 = gb1; ga1 = ga2; gb1 = gb2; ga2 = nga; gb2 = ngb;
            }
        }
    }
    g_agg[(size_t)n * HH + lane] = accA;
    g_agg[(size_t)n * HH + lane + 32] = accB;
}

// ---------------- fused node update (packed, two-phase weights) ----------------
__global__ __launch_bounds__(256) void kNode(int xSel, const float* __restrict__ xExt,
                                             int xOutSel,
                                             const float* __restrict__ W2,
                                             const float* __restrict__ b2,
                                             const float* __restrict__ V1,
                                             const float* __restrict__ c1,
                                             const float* __restrict__ V2,
                                             const float* __restrict__ c2,
                                             const float* __restrict__ W1n,
                                             const float* __restrict__ b1n,
                                             const float* __restrict__ epsPtr,
                                             const void* __restrict__ batch, int layer) {
    __shared__ __align__(16) ull sA[16][64];
    __shared__ __align__(16) ull sB[16][64];
    int tid = threadIdx.x;
    int c = tid & 63, rs = tid >> 6;
    int base = blockIdx.x * 32;
    const float* X = pickIn(xSel, xExt);
    float* Xo = pickOut(xOutSel);

    stageX(g_agg, (float*)sA, base, tid);
    __syncthreads();

    ull acc[4];

    // ---- stage 1: u = agg@W2 + (1+eps)*x + cnt*b2 ----
    gemmP(sA, W2, c, rs, acc);
    {
        float bv = b2[c];
        float ope = 1.f + epsPtr[0];
#pragma unroll
        for (int i = 0; i < 4; i++) {
            int rp = rs + 4 * i;
            int r0 = base + 2 * rp, r1 = r0 + 1;
            float a0, a1; upk2(acc[i], a0, a1);
            float x0 = (r0 < NN) ? X[(size_t)r0 * HH + c] : 0.f;
            float x1 = (r1 < NN) ? X[(size_t)r1 * HH + c] : 0.f;
            float n0 = (r0 < NN) ? (float)g_cnt[r0] : 0.f;
            float n1 = (r1 < NN) ? (float)g_cnt[r1] : 0.f;
            a0 += ope * x0 + n0 * bv;
            a1 += ope * x1 + n1 * bv;
            sB[rp][c] = pk2(a0, a1);
        }
    }
    __syncthreads();

    // ---- stage 2: h = relu(u@V1 + c1) ----
    gemmP(sB, V1, c, rs, acc);
    {
        float bv = c1[c];
#pragma unroll
        for (int i = 0; i < 4; i++) {
            float a0, a1; upk2(acc[i], a0, a1);
            sA[rs + 4 * i][c] = pk2(fmaxf(a0 + bv, 0.f), fmaxf(a1 + bv, 0.f));
        }
    }
    __syncthreads();

    // ---- stage 3: xn = h@V2 + c2 ; write x_next + pool atomics ----
    gemmP(sA, V2, c, rs, acc);
    {
        float bv = c2[c];
        int f64 = g_flag64;
#pragma unroll
        for (int i = 0; i < 4; i++) {
            int rp = rs + 4 * i;
            int r0 = base + 2 * rp, r1 = r0 + 1;
            float a0, a1; upk2(acc[i], a0, a1);
            float v0 = a0 + bv, v1 = a1 + bv;
            sB[rp][c] = pk2(v0, v1);
            if (r0 < NN) {
                Xo[(size_t)r0 * HH + c] = v0;
                int g = f64 ? (int)((const long long*)batch)[r0] : ((const int*)batch)[r0];
                atomicAdd(&g_pool[(size_t)g * FD + layer * HH + c], v0);
            }
            if (r1 < NN) {
                Xo[(size_t)r1 * HH + c] = v1;
                int g = f64 ? (int)((const long long*)batch)[r1] : ((const int*)batch)[r1];
                atomicAdd(&g_pool[(size_t)g * FD + layer * HH + c], v1);
            }
        }
    }

    // ---- stage 4: t1_next = xn@W1a_next + b1_next ----
    if (W1n) {
        __syncthreads();
        gemmP(sB, W1n, c, rs, acc);
        float bv = b1n[c];
#pragma unroll
        for (int i = 0; i < 4; i++) {
            int r0 = base + 2 * (rs + 4 * i), r1 = r0 + 1;
            float a0, a1; upk2(acc[i], a0, a1);
            if (r0 < NN) g_t1[(size_t)r0 * HH + c] = a0 + bv;
            if (r1 < NN) g_t1[(size_t)r1 * HH + c] = a1 + bv;
        }
    }
}

// ---------------- final MLP ----------------
__global__ __launch_bounds__(320) void kFinal(const float* __restrict__ fw1,
                                              const float* __restrict__ fb1,
                                              const float* __restrict__ fw2,
                                              const float* __restrict__ fb2,
                                              float* __restrict__ out) {
    __shared__ float fsh[8][FD];
    __shared__ float hsh[8][FD];
    int tid = threadIdx.x;
    int gbase = blockIdx.x * 8;
    for (int i = tid; i < 8 * FD; i += 320) {
        int gg = i / FD, k = i % FD;
        fsh[gg][k] = g_pool[(size_t)(gbase + gg) * FD + k];
    }
    __syncthreads();
    float acc[8] = {0, 0, 0, 0, 0, 0, 0, 0};
    for (int k = 0; k < FD; k++) {
        float w = fw1[(size_t)k * FD + tid];
#pragma unroll
        for (int gg = 0; gg < 8; gg++) acc[gg] = fmaf(fsh[gg][k], w, acc[gg]);
    }
    float b = fb1[tid];
#pragma unroll
    for (int gg = 0; gg < 8; gg++) hsh[gg][tid] = fmaxf(acc[gg] + b, 0.f);
    __syncthreads();
    int warp = tid >> 5, lane = tid & 31;
    if (warp < 8) {
        float s = 0.f;
        for (int k = lane; k < FD; k += 32) s += hsh[warp][k] * fw2[k];
#pragma unroll
        for (int o = 16; o; o >>= 1) s += __shfl_down_sync(0xffffffffu, s, o);
        if (lane == 0) out[gbase + warp] = s + fb2[0];
    }
}

// ---------------- launch ----------------
extern "C" void kernel_launch(void* const* d_in, const int* in_sizes, int n_in,
                              void* d_out, int out_size) {
    const float* x    = (const float*)d_in[0];
    const void*  ei   = d_in[1];
    const float* ea   = (const float*)d_in[2];
    const void*  bat  = d_in[3];
    const float* n2w1 = (const float*)d_in[4];
    const float* n2b1 = (const float*)d_in[5];
    const float* n2w2 = (const float*)d_in[6];
    const float* n2b2 = (const float*)d_in[7];
    const float* n1w1 = (const float*)d_in[8];
    const float* n1b1 = (const float*)d_in[9];
    const float* n1w2 = (const float*)d_in[10];
    const float* n1b2 = (const float*)d_in[11];
    const float* fw1  = (const float*)d_in[12];
    const float* fb1  = (const float*)d_in[13];
    const float* fw2  = (const float*)d_in[14];
    const float* fb2  = (const float*)d_in[15];
    const float* eps  = (const float*)d_in[16];

    kDetect<<<1, 1>>>(ei);
    kZero<<<(GG * FD + 255) / 256, 256>>>();
    kCount<<<EE / 256, 256>>>(ei);
    // launch #4 = kT1 so ncu captures the GEMM core
    kT1<<<(NN + 31) / 32, 256>>>(x, n2w1, n2b1);
    kScanA<<<NBLK, 1024>>>();
    kScanB<<<1, 32>>>();
    kScanC<<<NBLK, 1024>>>();
    kScatter<<<EE / 256, 256>>>(ei, ea);

    int xSel = 4;
    const float* xPtr = x;
    for (int l = 0; l < LLAY; l++) {
        const float* W2 = n2w2 + (size_t)l * HH * HH;
        const float* b2 = n2b2 + (size_t)l * HH;
        const float* V1 = n1w1 + (size_t)l * HH * HH;
        const float* c1 = n1b1 + (size_t)l * HH;
        const float* V2 = n1w2 + (size_t)l * HH * HH;
        const float* c2 = n1b2 + (size_t)l * HH;
        const float* W1n = (l + 1 < LLAY) ? n2w1 + (size_t)(l + 1) * IN2 * HH : nullptr;
        const float* b1n = (l + 1 < LLAY) ? n2b1 + (size_t)(l + 1) * HH : nullptr;
        int xNextSel = (l & 1) ? 3 : 2;

        kAgg<<<NN / 8, 256>>>(n2w1 + (size_t)l * IN2 * HH);
        kNode<<<(NN + 31) / 32, 256>>>(xSel, xPtr, xNextSel, W2, b2, V1, c1, V2, c2,
                                       W1n, b1n, eps, bat, l);

        xSel = xNextSel;
        xPtr = nullptr;
    }

    kFinal<<<GG / 8, 320>>>(fw1, fb1, fw2, fb2, (float*)d_out);
}

// round 7
// speedup vs baseline: 1.6223x; 1.2072x over previous
#include <cuda_runtime.h>
#include <cuda_bf16.h>
#include <cstdint>

#define NN   50000
#define EE   800000
#define HH   64
#define EAD  16
#define LLAY 5
#define GG   512
#define IN2  80
#define FD   320   // L*H
#define NBLK 49    // ceil(NN/1024)
#define CHK  256   // edges staged per kAgg chunk
#define NBM  782   // ceil(NN/64)
#define SP   72    // smem row stride (bf16 elems) -> conflict-free fragment LDS

typedef unsigned long long ull;

// ---------------- device scratch ----------------
__device__ int   g_flag64;
__device__ int   g_cnt[NN];
__device__ int   g_off[NN + 1];
__device__ int   g_cur[NN];
__device__ int   g_bsum[NBLK];
__device__ int   g_srcS[EE];
__device__ __align__(16) float g_eaS[(size_t)EE * EAD];   // edge_attr sorted by dst
__device__ __align__(16) float g_t1[(size_t)NN * HH];     // x@W1a + b1
__device__ __align__(16) float g_agg[(size_t)NN * HH];
__device__ __align__(16) float g_xA[(size_t)NN * HH];
__device__ __align__(16) float g_xB[(size_t)NN * HH];
__device__ float g_pool[(size_t)GG * FD];
// packed bf16 weights: slot m = layer*4+stage (stage0=W2,1=V1,2=V2,3=W1a_next)
// layout [m][hi/lo][n][k] with k-stride SP, element (n,k) = W_orig[k][n]
__device__ __align__(16) __nv_bfloat16 g_wB[20][2][64][SP];

// ---------------- f32x2 packed helpers (SIMT kernels) ----------------
__device__ __forceinline__ ull pk2(float a, float b) {
    ull r; asm("mov.b64 %0,{%1,%2};" : "=l"(r) : "f"(a), "f"(b)); return r;
}
__device__ __forceinline__ void upk2(ull v, float& a, float& b) {
    asm("mov.b64 {%0,%1},%2;" : "=f"(a), "=f"(b) : "l"(v));
}
__device__ __forceinline__ ull fma2(ull a, ull b, ull c) {
    ull d; asm("fma.rn.f32x2 %0,%1,%2,%3;" : "=l"(d) : "l"(a), "l"(b), "l"(c)); return d;
}

__device__ __forceinline__ int loadIdx(const void* p, long long i, int is64) {
    if (is64) return (int)((const long long*)p)[i];
    return ((const int*)p)[i];
}
__device__ __forceinline__ const float* pickIn(int sel, const float* xin) {
    switch (sel) { case 2: return g_xA; case 3: return g_xB; default: return xin; }
}
__device__ __forceinline__ float* pickOut(int sel) { return (sel == 2) ? g_xA : g_xB; }

// ---------------- bf16 pack helpers ----------------
__device__ __forceinline__ unsigned pbHi(float x, float y) {
    __nv_bfloat16 hx = __float2bfloat16(x), hy = __float2bfloat16(y);
    return (unsigned)__bfloat16_as_ushort(hx) | ((unsigned)__bfloat16_as_ushort(hy) << 16);
}
__device__ __forceinline__ unsigned pbLo(float x, float y) {
    __nv_bfloat16 hx = __float2bfloat16(x), hy = __float2bfloat16(y);
    float lx = x - __bfloat162float(hx), ly = y - __bfloat162float(hy);
    __nv_bfloat16 bx = __float2bfloat16(lx), by = __float2bfloat16(ly);
    return (unsigned)__bfloat16_as_ushort(bx) | ((unsigned)__bfloat16_as_ushort(by) << 16);
}

// ---------------- mma.sync m16n8k16 bf16 ----------------
__device__ __forceinline__ void mma16816(float* c, unsigned a0, unsigned a1,
                                         unsigned a2, unsigned a3,
                                         unsigned b0, unsigned b1) {
    asm volatile(
        "mma.sync.aligned.m16n8k16.row.col.f32.bf16.bf16.f32 "
        "{%0,%1,%2,%3}, {%4,%5,%6,%7}, {%8,%9}, {%0,%1,%2,%3};"
        : "+f"(c[0]), "+f"(c[1]), "+f"(c[2]), "+f"(c[3])
        : "r"(a0), "r"(a1), "r"(a2), "r"(a3), "r"(b0), "r"(b1));
}

// ---------------- setup ----------------
__global__ void kDetect(const void* ei) {
    const int* p = (const int*)ei;
    g_flag64 = (p[1] == 0 && p[3] == 0 && p[5] == 0 && p[7] == 0) ? 1 : 0;
}
__global__ void kZero() {
    int i = blockIdx.x * blockDim.x + threadIdx.x;
    if (i < NN) g_cnt[i] = 0;
    if (i < GG * FD) g_pool[i] = 0.f;
}
__global__ void kCount(const void* __restrict__ ei) {
    int e = blockIdx.x * blockDim.x + threadIdx.x;
    if (e >= EE) return;
    int f = g_flag64;
    int s = loadIdx(ei, e, f);
    int d = loadIdx(ei, (long long)EE + e, f);
    if (s != d) atomicAdd(&g_cnt[d], 1);
}
__global__ void kScanA() {
    __shared__ int wsum[32];
    int tid = threadIdx.x, lane = tid & 31, wid = tid >> 5;
    int i = blockIdx.x * 1024 + tid;
    int v = (i < NN) ? g_cnt[i] : 0;
    int x = v;
#pragma unroll
    for (int o = 1; o < 32; o <<= 1) {
        int t = __shfl_up_sync(0xffffffffu, x, o);
        if (lane >= o) x += t;
    }
    if (lane == 31) wsum[wid] = x;
    __syncthreads();
    if (tid < 32) {
        int y = wsum[tid];
#pragma unroll
        for (int o = 1; o < 32; o <<= 1) {
            int t = __shfl_up_sync(0xffffffffu, y, o);
            if (tid >= o) y += t;
        }
        wsum[tid] = y;
    }
    __syncthreads();
    int incl = x + (wid ? wsum[wid - 1] : 0);
    if (i < NN) g_off[i] = incl - v;
    if (tid == 1023) g_bsum[blockIdx.x] = incl;
}
__global__ void kScanB() {
    if (threadIdx.x == 0) {
        int s = 0;
        for (int b = 0; b < NBLK; b++) { int t = g_bsum[b]; g_bsum[b] = s; s += t; }
        g_off[NN] = s;
    }
}
__global__ void kScanC() {
    int i = blockIdx.x * 1024 + threadIdx.x;
    if (i < NN) {
        int v = g_off[i] + g_bsum[blockIdx.x];
        g_off[i] = v;
        g_cur[i] = v;
    }
}
__global__ void kScatter(const void* __restrict__ ei, const float* __restrict__ ea) {
    int e = blockIdx.x * blockDim.x + threadIdx.x;
    if (e >= EE) return;
    int f = g_flag64;
    int s = loadIdx(ei, e, f);
    int d = loadIdx(ei, (long long)EE + e, f);
    if (s == d) return;
    int pos = atomicAdd(&g_cur[d], 1);
    g_srcS[pos] = s;
    const float4* s4 = (const float4*)(ea + (size_t)e * EAD);
    float4* d4 = (float4*)(g_eaS + (size_t)pos * EAD);
    d4[0] = s4[0]; d4[1] = s4[1]; d4[2] = s4[2]; d4[3] = s4[3];
}

// ---------------- weight pack: fp32 [k][c] -> bf16 hi/lo, [n=c][k] stride SP ----------------
__global__ void kPackW(const float* __restrict__ n2w1, const float* __restrict__ n2w2,
                       const float* __restrict__ n1w1, const float* __restrict__ n1w2) {
    int idx = blockIdx.x * 256 + threadIdx.x;
    if (idx >= 20 * 4096) return;
    int m = idx / 4096;
    int e = idx % 4096;
    int k = e >> 6, c = e & 63;
    int l = m >> 2, s = m & 3;
    float v;
    if (s == 0)      v = n2w2[((size_t)l * 64 + k) * 64 + c];
    else if (s == 1) v = n1w1[((size_t)l * 64 + k) * 64 + c];
    else if (s == 2) v = n1w2[((size_t)l * 64 + k) * 64 + c];
    else             v = (l < 4) ? n2w1[((size_t)(l + 1) * 80 + k) * 64 + c] : 0.f;
    __nv_bfloat16 hi = __float2bfloat16(v);
    __nv_bfloat16 lo = __float2bfloat16(v - __bfloat162float(hi));
    g_wB[m][0][c][k] = hi;
    g_wB[m][1][c][k] = lo;
}

// ---------------- packed 32-row SIMT GEMM (kT1 only) ----------------
__device__ __forceinline__ void gemmP(const ull (*sIn)[64], const float* __restrict__ W,
                                      int c, int rs, ull* acc) {
#pragma unroll
    for (int i = 0; i < 4; i++) acc[i] = 0ull;
#pragma unroll 1
    for (int h = 0; h < 2; h++) {
        float w[32];
#pragma unroll
        for (int k = 0; k < 32; k++) w[k] = W[(32 * h + k) * HH + c];
#pragma unroll
        for (int kp = 0; kp < 16; kp++) {
            ull wd0 = pk2(w[2 * kp], w[2 * kp]);
            ull wd1 = pk2(w[2 * kp + 1], w[2 * kp + 1]);
#pragma unroll
            for (int i = 0; i < 4; i++) {
                ulonglong2 v = *(const ulonglong2*)&sIn[rs + 4 * i][32 * h + 2 * kp];
                acc[i] = fma2(v.x, wd0, acc[i]);
                acc[i] = fma2(v.y, wd1, acc[i]);
            }
        }
    }
}
__device__ __forceinline__ void stageX(const float* __restrict__ src, float* sf,
                                       int base, int tid) {
    for (int i = tid; i < 2048; i += 256) {
        int r = i >> 6, cc = i & 63;
        int gr = base + r;
        sf[((r >> 1) * 64 + cc) * 2 + (r & 1)] = (gr < NN) ? src[(size_t)gr * HH + cc] : 0.f;
    }
}

// ---------------- t1 = x @ W1a + b1 (layer 0, SIMT exact) ----------------
__global__ __launch_bounds__(256) void kT1(const float* __restrict__ X,
                                           const float* __restrict__ W,
                                           const float* __restrict__ B) {
    __shared__ __align__(16) ull sIn[16][64];
    int tid = threadIdx.x;
    int c = tid & 63, rs = tid >> 6;
    int base = blockIdx.x * 32;
    stageX(X, (float*)sIn, base, tid);
    __syncthreads();
    ull acc[4];
    gemmP(sIn, W, c, rs, acc);
    float b = B[c];
#pragma unroll
    for (int i = 0; i < 4; i++) {
        int r0 = base + 2 * (rs + 4 * i), r1 = r0 + 1;
        float a0, a1; upk2(acc[i], a0, a1);
        if (r0 < NN) g_t1[(size_t)r0 * HH + c] = a0 + b;
        if (r1 < NN) g_t1[(size_t)r1 * HH + c] = a1 + b;
    }
}

// ---------------- edge aggregation (unchanged) ----------------
__global__ __launch_bounds__(256) void kAgg(const float* __restrict__ w1full) {
    __shared__ __align__(16) float sea[CHK * EAD];
    __shared__ int ssrc[CHK];
    int tid = threadIdx.x;
    int lane = tid & 31, warp = tid >> 5;
    const float* w1b = w1full + 64 * HH;
    ull wA2[8], wB2[8];
#pragma unroll
    for (int p = 0; p < 8; p++) {
        wA2[p] = pk2(w1b[(2 * p) * HH + lane],      w1b[(2 * p + 1) * HH + lane]);
        wB2[p] = pk2(w1b[(2 * p) * HH + lane + 32], w1b[(2 * p + 1) * HH + lane + 32]);
    }
    int nb = blockIdx.x * 8;
    int n = nb + warp;
    int beg = g_off[n], end = g_off[n + 1];
    int bBeg = g_off[nb], bEnd = g_off[nb + 8];
    float accA = 0.f, accB = 0.f;

    for (int cb = bBeg; cb < bEnd; cb += CHK) {
        int cnt = min(CHK, bEnd - cb);
        __syncthreads();
        for (int i = tid; i < cnt * 4; i += 256)
            ((float4*)sea)[i] = ((const float4*)g_eaS)[(size_t)cb * 4 + i];
        for (int i = tid; i < cnt; i += 256) ssrc[i] = g_srcS[cb + i];
        __syncthreads();

        int myB = max(beg, cb), myE = min(end, cb + cnt);
        int m = myE - myB;
        if (m > 0) {
            int q0 = myB - cb;
            float ga0, gb0, ga1 = 0.f, gb1 = 0.f, ga2 = 0.f, gb2 = 0.f;
            { int s = ssrc[q0];
              ga0 = g_t1[(size_t)s * HH + lane]; gb0 = g_t1[(size_t)s * HH + lane + 32]; }
            if (m > 1) { int s = ssrc[q0 + 1];
              ga1 = g_t1[(size_t)s * HH + lane]; gb1 = g_t1[(size_t)s * HH + lane + 32]; }
            if (m > 2) { int s = ssrc[q0 + 2];
              ga2 = g_t1[(size_t)s * HH + lane]; gb2 = g_t1[(size_t)s * HH + lane + 32]; }
            for (int q = 0; q < m; q++) {
                float nga = 0.f, ngb = 0.f;
                if (q + 3 < m) {
                    int s = ssrc[q0 + q + 3];
                    nga = g_t1[(size_t)s * HH + lane];
                    ngb = g_t1[(size_t)s * HH + lane + 32];
                }
                const ulonglong2* ep = (const ulonglong2*)(sea + (size_t)(q0 + q) * EAD);
                ull tA = pk2(ga0, 0.f), tB = pk2(gb0, 0.f);
#pragma unroll
                for (int p = 0; p < 4; p++) {
                    ulonglong2 v = ep[p];
                    tA = fma2(v.x, wA2[2 * p], tA);
                    tB = fma2(v.x, wB2[2 * p], tB);
                    tA = fma2(v.y, wA2[2 * p + 1], tA);
                    tB = fma2(v.y, wB2[2 * p + 1], tB);
                }
                float a0, a1, b0, b1;
                upk2(tA, a0, a1); upk2(tB, b0, b1);
                accA += fmaxf(a0 + a1, 0.f);
                accB += fmaxf(b0 + b1, 0.f);
                ga0 = ga1; gb0 = gb1; ga1 = ga2; gb1 = gb2; ga2 = nga; gb2 = ngb;
            }
        }
    }
    g_agg[(size_t)n * HH + lane] = accA;
    g_agg[(size_t)n * HH + lane + 32] = accB;
}

// ---------------- mma.sync fused node update ----------------
// block: 64 nodes, 128 threads = 4 warps, warp w -> rows [w*16, w*16+16)
// stages: 0: u = agg@W2 + (1+eps)x + cnt*b2
//         1: h = relu(u@V1 + c1)
//         2: xn = h@V2 + c2 (store + pool)
//         3: t1' = xn@W1a' + b1'   (layers 0..3 only)
__global__ __launch_bounds__(128) void kNodeM(int xSel, const float* __restrict__ xExt,
                                              int xOutSel,
                                              const float* __restrict__ b2,
                                              const float* __restrict__ c1,
                                              const float* __restrict__ c2,
                                              const float* __restrict__ b1n,
                                              const float* __restrict__ epsPtr,
                                              const void* __restrict__ batch, int layer) {
    __shared__ __align__(16) __nv_bfloat16 sAhi[64][SP];
    __shared__ __align__(16) __nv_bfloat16 sAlo[64][SP];
    __shared__ __align__(16) __nv_bfloat16 sWhi[64][SP];
    __shared__ __align__(16) __nv_bfloat16 sWlo[64][SP];
    __shared__ float sBias[4][64];

    int tid = threadIdx.x, lane = tid & 31, warp = tid >> 5;
    int g8 = lane >> 2, tg = lane & 3;
    int base = blockIdx.x * 64;
    const float* X = pickIn(xSel, xExt);
    float* Xo = pickOut(xOutSel);
    int nStages = (layer < LLAY - 1) ? 4 : 3;

    if (tid < 64) {
        sBias[0][tid] = b2[tid];
        sBias[1][tid] = c1[tid];
        sBias[2][tid] = c2[tid];
        sBias[3][tid] = b1n ? b1n[tid] : 0.f;
    }
    // initial A <- agg (hi/lo split), zero-pad invalid rows
    for (int i = tid; i < 4096; i += 128) {
        int r = i >> 6, cc = i & 63;
        int gr = base + r;
        float v = (gr < NN) ? g_agg[(size_t)gr * HH + cc] : 0.f;
        __nv_bfloat16 h = __float2bfloat16(v);
        sAhi[r][cc] = h;
        sAlo[r][cc] = __float2bfloat16(v - __bfloat162float(h));
    }
    // stage-0 weights
    {
        const float4* sH = (const float4*)&g_wB[layer * 4][0][0][0];
        const float4* sL = (const float4*)&g_wB[layer * 4][1][0][0];
        float4* dH = (float4*)&sWhi[0][0];
        float4* dL = (float4*)&sWlo[0][0];
        for (int i = tid; i < 576; i += 128) { dH[i] = sH[i]; dL[i] = sL[i]; }
    }

    // per-thread row constants (fragment rows)
    int lr0 = warp * 16 + g8, lr1 = lr0 + 8;
    int r0 = base + lr0, r1 = base + lr1;
    bool valid0 = r0 < NN, valid1 = r1 < NN;
    float ope = 1.f + epsPtr[0];
    float cnt0 = valid0 ? (float)g_cnt[r0] : 0.f;
    float cnt1 = valid1 ? (float)g_cnt[r1] : 0.f;
    int f64 = g_flag64;
    int gb0 = valid0 ? loadIdx(batch, r0, f64) : 0;
    int gb1 = valid1 ? loadIdx(batch, r1, f64) : 0;

    for (int s = 0; s < nStages; s++) {
        __syncthreads();                // sA + sW ready
        float acc[8][4];
#pragma unroll
        for (int nt = 0; nt < 8; nt++)
#pragma unroll
            for (int j = 0; j < 4; j++) acc[nt][j] = 0.f;

#pragma unroll
        for (int k = 0; k < 4; k++) {
            int k0 = k * 16 + tg * 2;
            unsigned ah0 = *(const unsigned*)&sAhi[lr0][k0];
            unsigned ah1 = *(const unsigned*)&sAhi[lr1][k0];
            unsigned ah2 = *(const unsigned*)&sAhi[lr0][k0 + 8];
            unsigned ah3 = *(const unsigned*)&sAhi[lr1][k0 + 8];
            unsigned al0 = *(const unsigned*)&sAlo[lr0][k0];
            unsigned al1 = *(const unsigned*)&sAlo[lr1][k0];
            unsigned al2 = *(const unsigned*)&sAlo[lr0][k0 + 8];
            unsigned al3 = *(const unsigned*)&sAlo[lr1][k0 + 8];
#pragma unroll
            for (int nt = 0; nt < 8; nt++) {
                int nr = nt * 8 + g8;
                unsigned bh0 = *(const unsigned*)&sWhi[nr][k0];
                unsigned bh1 = *(const unsigned*)&sWhi[nr][k0 + 8];
                unsigned bl0 = *(const unsigned*)&sWlo[nr][k0];
                unsigned bl1 = *(const unsigned*)&sWlo[nr][k0 + 8];
                mma16816(acc[nt], ah0, ah1, ah2, ah3, bh0, bh1);
                mma16816(acc[nt], ah0, ah1, ah2, ah3, bl0, bl1);
                mma16816(acc[nt], al0, al1, al2, al3, bh0, bh1);
            }
        }
        __syncthreads();                // done reading sA / sW

        if (s + 1 < nStages) {          // prefetch next-stage weights
            const float4* sH = (const float4*)&g_wB[layer * 4 + s + 1][0][0][0];
            const float4* sL = (const float4*)&g_wB[layer * 4 + s + 1][1][0][0];
            float4* dH = (float4*)&sWhi[0][0];
            float4* dL = (float4*)&sWlo[0][0];
            for (int i = tid; i < 576; i += 128) { dH[i] = sH[i]; dL[i] = sL[i]; }
        }

        bool last = (s == nStages - 1);
#pragma unroll
        for (int nt = 0; nt < 8; nt++) {
            int col0 = nt * 8 + tg * 2;
            float v00, v01, v10, v11;
            if (s == 0) {
                float2 x0 = valid0 ? *(const float2*)&X[(size_t)r0 * HH + col0]
                                   : make_float2(0.f, 0.f);
                float2 x1 = valid1 ? *(const float2*)&X[(size_t)r1 * HH + col0]
                                   : make_float2(0.f, 0.f);
                v00 = acc[nt][0] + ope * x0.x + cnt0 * sBias[0][col0];
                v01 = acc[nt][1] + ope * x0.y + cnt0 * sBias[0][col0 + 1];
                v10 = acc[nt][2] + ope * x1.x + cnt1 * sBias[0][col0];
                v11 = acc[nt][3] + ope * x1.y + cnt1 * sBias[0][col0 + 1];
            } else if (s == 1) {
                v00 = fmaxf(acc[nt][0] + sBias[1][col0], 0.f);
                v01 = fmaxf(acc[nt][1] + sBias[1][col0 + 1], 0.f);
                v10 = fmaxf(acc[nt][2] + sBias[1][col0], 0.f);
                v11 = fmaxf(acc[nt][3] + sBias[1][col0 + 1], 0.f);
            } else if (s == 2) {
                v00 = acc[nt][0] + sBias[2][col0];
                v01 = acc[nt][1] + sBias[2][col0 + 1];
                v10 = acc[nt][2] + sBias[2][col0];
                v11 = acc[nt][3] + sBias[2][col0 + 1];
                if (valid0) {
                    *(float2*)&Xo[(size_t)r0 * HH + col0] = make_float2(v00, v01);
                    atomicAdd(&g_pool[(size_t)gb0 * FD + layer * HH + col0], v00);
                    atomicAdd(&g_pool[(size_t)gb0 * FD + layer * HH + col0 + 1], v01);
                }
                if (valid1) {
                    *(float2*)&Xo[(size_t)r1 * HH + col0] = make_float2(v10, v11);
                    atomicAdd(&g_pool[(size_t)gb1 * FD + layer * HH + col0], v10);
                    atomicAdd(&g_pool[(size_t)gb1 * FD + layer * HH + col0 + 1], v11);
                }
            } else {
                v00 = acc[nt][0] + sBias[3][col0];
                v01 = acc[nt][1] + sBias[3][col0 + 1];
                v10 = acc[nt][2] + sBias[3][col0];
                v11 = acc[nt][3] + sBias[3][col0 + 1];
                if (valid0) *(float2*)&g_t1[(size_t)r0 * HH + col0] = make_float2(v00, v01);
                if (valid1) *(float2*)&g_t1[(size_t)r1 * HH + col0] = make_float2(v10, v11);
            }
            if (!last) {
                *(unsigned*)&sAhi[lr0][col0] = pbHi(v00, v01);
                *(unsigned*)&sAlo[lr0][col0] = pbLo(v00, v01);
                *(unsigned*)&sAhi[lr1][col0] = pbHi(v10, v11);
                *(unsigned*)&sAlo[lr1][col0] = pbLo(v10, v11);
            }
        }
    }
}

// ---------------- final MLP ----------------
__global__ __launch_bounds__(320) void kFinal(const float* __restrict__ fw1,
                                              const float* __restrict__ fb1,
                                              const float* __restrict__ fw2,
                                              const float* __restrict__ fb2,
                                              float* __restrict__ out) {
    __shared__ float fsh[8][FD];
    __shared__ float hsh[8][FD];
    int tid = threadIdx.x;
    int gbase = blockIdx.x * 8;
    for (int i = tid; i < 8 * FD; i += 320) {
        int gg = i / FD, k = i % FD;
        fsh[gg][k] = g_pool[(size_t)(gbase + gg) * FD + k];
    }
    __syncthreads();
    float acc[8] = {0, 0, 0, 0, 0, 0, 0, 0};
    for (int k = 0; k < FD; k++) {
        float w = fw1[(size_t)k * FD + tid];
#pragma unroll
        for (int gg = 0; gg < 8; gg++) acc[gg] = fmaf(fsh[gg][k], w, acc[gg]);
    }
    float b = fb1[tid];
#pragma unroll
    for (int gg = 0; gg < 8; gg++) hsh[gg][tid] = fmaxf(acc[gg] + b, 0.f);
    __syncthreads();
    int warp = tid >> 5, lane = tid & 31;
    if (warp < 8) {
        float s = 0.f;
        for (int k = lane; k < FD; k += 32) s += hsh[warp][k] * fw2[k];
#pragma unroll
        for (int o = 16; o; o >>= 1) s += __shfl_down_sync(0xffffffffu, s, o);
        if (lane == 0) out[gbase + warp] = s + fb2[0];
    }
}

// ---------------- launch ----------------
extern "C" void kernel_launch(void* const* d_in, const int* in_sizes, int n_in,
                              void* d_out, int out_size) {
    const float* x    = (const float*)d_in[0];
    const void*  ei   = d_in[1];
    const float* ea   = (const float*)d_in[2];
    const void*  bat  = d_in[3];
    const float* n2w1 = (const float*)d_in[4];
    const float* n2b1 = (const float*)d_in[5];
    const float* n2w2 = (const float*)d_in[6];
    const float* n2b2 = (const float*)d_in[7];
    const float* n1w1 = (const float*)d_in[8];
    const float* n1b1 = (const float*)d_in[9];
    const float* n1w2 = (const float*)d_in[10];
    const float* n1b2 = (const float*)d_in[11];
    const float* fw1  = (const float*)d_in[12];
    const float* fb1  = (const float*)d_in[13];
    const float* fw2  = (const float*)d_in[14];
    const float* fb2  = (const float*)d_in[15];
    const float* eps  = (const float*)d_in[16];

    kDetect<<<1, 1>>>(ei);
    kZero<<<(GG * FD + 255) / 256, 256>>>();
    kCount<<<EE / 256, 256>>>(ei);
    kT1<<<(NN + 31) / 32, 256>>>(x, n2w1, n2b1);       // profile slot
    kPackW<<<(20 * 4096 + 255) / 256, 256>>>(n2w1, n2w2, n1w1, n1w2);
    kScanA<<<NBLK, 1024>>>();
    kScanB<<<1, 32>>>();
    kScanC<<<NBLK, 1024>>>();
    kScatter<<<EE / 256, 256>>>(ei, ea);

    int xSel = 4;
    const float* xPtr = x;
    for (int l = 0; l < LLAY; l++) {
        const float* b2 = n2b2 + (size_t)l * HH;
        const float* c1 = n1b1 + (size_t)l * HH;
        const float* c2 = n1b2 + (size_t)l * HH;
        const float* b1n = (l + 1 < LLAY) ? n2b1 + (size_t)(l + 1) * HH : nullptr;
        int xNextSel = (l & 1) ? 3 : 2;

        kAgg<<<NN / 8, 256>>>(n2w1 + (size_t)l * IN2 * HH);
        kNodeM<<<NBM, 128>>>(xSel, xPtr, xNextSel, b2, c1, c2, b1n, eps, bat, l);

        xSel = xNextSel;
        xPtr = nullptr;
    }

    kFinal<<<GG / 8, 320>>>(fw1, fb1, fw2, fb2, (float*)d_out);
}